// round 1
// baseline (speedup 1.0000x reference)
#include <cuda_runtime.h>
#include <math.h>

#define BB 16
#define TT 2048
#define CC 68
#define HH 64
#define BT (BB*TT)
#define BQ 64
#define BK 64
#define STR 68          // smem row stride in floats (keeps 16B alignment, 272B row)
#define NKT (TT/BK)

// Scratch for projected Q (pre-scaled by 1/8), K, V: 3 x 8 MB fp32.
__device__ float g_Q[BT*HH];
__device__ float g_K[BT*HH];
__device__ float g_V[BT*HH];

// ---------------------------------------------------------------------------
// Kernel 1: fused QKV projection. Block = 16 rows of x, 256 threads.
// Thread (rg, h) computes 4 rows for one output column h of all 3 matrices,
// so each W element load feeds 12 FMAs.
// ---------------------------------------------------------------------------
__global__ __launch_bounds__(256) void proj_kernel(
    const float* __restrict__ x,
    const float* __restrict__ Wk,
    const float* __restrict__ Wq,
    const float* __restrict__ Wv)
{
    __shared__ float sx[16][CC];
    const int row0 = blockIdx.x * 16;
    const int tid  = threadIdx.x;

    for (int i = tid; i < 16*CC; i += 256)
        sx[i / CC][i % CC] = x[row0*CC + i];
    __syncthreads();

    const int h  = tid & 63;
    const int rg = tid >> 6;   // 0..3, each handles 4 rows

    float ak[4] = {0.f,0.f,0.f,0.f};
    float aq[4] = {0.f,0.f,0.f,0.f};
    float av[4] = {0.f,0.f,0.f,0.f};

    #pragma unroll 4
    for (int c = 0; c < CC; c++) {
        const float wk = Wk[c*HH + h];
        const float wq = Wq[c*HH + h];
        const float wv = Wv[c*HH + h];
        #pragma unroll
        for (int d = 0; d < 4; d++) {
            const float xv = sx[rg*4 + d][c];
            ak[d] = fmaf(xv, wk, ak[d]);
            aq[d] = fmaf(xv, wq, aq[d]);
            av[d] = fmaf(xv, wv, av[d]);
        }
    }

    #pragma unroll
    for (int d = 0; d < 4; d++) {
        const int row = row0 + rg*4 + d;
        g_K[row*HH + h] = ak[d];
        g_Q[row*HH + h] = aq[d] * 0.125f;   // fold 1/sqrt(64) into Q
        g_V[row*HH + h] = av[d];
    }
}

// ---------------------------------------------------------------------------
// Kernel 2: flash attention, fp32. CTA = one 64-row Q tile of one batch.
// 256 threads as 16x16 grid; each thread owns a 4x4 micro-tile of S and of O.
// Online softmax; P goes through smem (transposed + swizzled) for the PV GEMM.
// ---------------------------------------------------------------------------
__global__ __launch_bounds__(256) void attn_kernel(float* __restrict__ out)
{
    extern __shared__ float sm[];
    float* sQt = sm;                 // [c][i]  c=head dim, i=q row
    float* sKt = sm + HH*STR;        // [c][j]  j=k row
    float* sV  = sm + 2*HH*STR;      // [j][h]
    float* sPt = sm + 3*HH*STR;      // [j][swizzled i-group]

    const int b  = blockIdx.y;
    const int qt = blockIdx.x;
    const int tid = threadIdx.x;
    const int tx = tid & 15, ty = tid >> 4;
    const int i0 = ty*4, j0 = tx*4, h0 = tx*4;

    const float* Qb = g_Q + (size_t)(b*TT + qt*BQ)*HH;
    const float* Kb = g_K + (size_t)b*TT*HH;
    const float* Vb = g_V + (size_t)b*TT*HH;

    // Stage Q tile transposed: sQt[h][i] = Q[i][h]
    for (int idx = tid; idx < BQ*HH; idx += 256) {
        const int i = idx >> 6, h = idx & 63;
        sQt[h*STR + i] = Qb[idx];
    }

    float m[4], l[4], o[4][4];
    #pragma unroll
    for (int d = 0; d < 4; d++) {
        m[d] = -INFINITY; l[d] = 0.f;
        #pragma unroll
        for (int e = 0; e < 4; e++) o[d][e] = 0.f;
    }

    for (int kt = 0; kt < NKT; kt++) {
        __syncthreads();   // prev iter done reading sKt/sV/sPt; Q staged (kt==0)
        {
            const float* Kt = Kb + (size_t)kt*BK*HH;
            const float* Vt = Vb + (size_t)kt*BK*HH;
            for (int idx = tid; idx < BK*HH; idx += 256) {
                const int j = idx >> 6, h = idx & 63;
                sKt[h*STR + j] = Kt[idx];
                sV [j*STR + h] = Vt[idx];
            }
        }
        __syncthreads();

        // ---- S = Q K^T (pre-scaled) ----
        float s[4][4] = {{0.f}};
        #pragma unroll 16
        for (int c = 0; c < HH; c++) {
            const float4 qv = *(const float4*)(sQt + c*STR + i0);
            const float4 kv = *(const float4*)(sKt + c*STR + j0);
            const float q4[4] = {qv.x, qv.y, qv.z, qv.w};
            const float k4[4] = {kv.x, kv.y, kv.z, kv.w};
            #pragma unroll
            for (int d = 0; d < 4; d++)
                #pragma unroll
                for (int e = 0; e < 4; e++)
                    s[d][e] = fmaf(q4[d], k4[e], s[d][e]);
        }

        // ---- online softmax (row reductions across the 16 tx lanes) ----
        #pragma unroll
        for (int d = 0; d < 4; d++) {
            float rm = fmaxf(fmaxf(s[d][0], s[d][1]), fmaxf(s[d][2], s[d][3]));
            rm = fmaxf(rm, __shfl_xor_sync(0xffffffffu, rm, 1));
            rm = fmaxf(rm, __shfl_xor_sync(0xffffffffu, rm, 2));
            rm = fmaxf(rm, __shfl_xor_sync(0xffffffffu, rm, 4));
            rm = fmaxf(rm, __shfl_xor_sync(0xffffffffu, rm, 8));

            const float mn    = fmaxf(m[d], rm);
            const float alpha = __expf(m[d] - mn);
            m[d] = mn;

            float rs = 0.f;
            #pragma unroll
            for (int e = 0; e < 4; e++) {
                s[d][e] = __expf(s[d][e] - mn);
                rs += s[d][e];
            }
            rs += __shfl_xor_sync(0xffffffffu, rs, 1);
            rs += __shfl_xor_sync(0xffffffffu, rs, 2);
            rs += __shfl_xor_sync(0xffffffffu, rs, 4);
            rs += __shfl_xor_sync(0xffffffffu, rs, 8);

            l[d] = l[d]*alpha + rs;
            #pragma unroll
            for (int e = 0; e < 4; e++) o[d][e] *= alpha;
        }

        // ---- store P^T swizzled: group g = (ty + (j>>2)) & 15 ----
        #pragma unroll
        for (int e = 0; e < 4; e++) {
            const int j = j0 + e;                 // j>>2 == tx
            const int g = (ty + tx) & 15;
            float* p = sPt + j*STR + g*4;
            p[0] = s[0][e]; p[1] = s[1][e]; p[2] = s[2][e]; p[3] = s[3][e];
        }
        __syncthreads();

        // ---- O += P V ----
        #pragma unroll 16
        for (int j = 0; j < BK; j++) {
            const int g = (ty + (j >> 2)) & 15;
            const float4 pv = *(const float4*)(sPt + j*STR + g*4);
            const float4 vv = *(const float4*)(sV  + j*STR + h0);
            const float p4[4] = {pv.x, pv.y, pv.z, pv.w};
            const float v4[4] = {vv.x, vv.y, vv.z, vv.w};
            #pragma unroll
            for (int d = 0; d < 4; d++)
                #pragma unroll
                for (int e = 0; e < 4; e++)
                    o[d][e] = fmaf(p4[d], v4[e], o[d][e]);
        }
    }

    // ---- epilogue: O / l ----
    float* Ob = out + (size_t)(b*TT + qt*BQ)*HH;
    #pragma unroll
    for (int d = 0; d < 4; d++) {
        const float inv = 1.f / l[d];
        const float4 r = make_float4(o[d][0]*inv, o[d][1]*inv,
                                     o[d][2]*inv, o[d][3]*inv);
        *(float4*)(Ob + (i0 + d)*HH + h0) = r;
    }
}

// ---------------------------------------------------------------------------
extern "C" void kernel_launch(void* const* d_in, const int* in_sizes, int n_in,
                              void* d_out, int out_size)
{
    const float* x  = (const float*)d_in[0];
    const float* Wk = (const float*)d_in[1];
    const float* Wq = (const float*)d_in[2];
    const float* Wv = (const float*)d_in[3];
    float* out = (float*)d_out;

    proj_kernel<<<BT/16, 256>>>(x, Wk, Wq, Wv);

    const int smem_bytes = 4 * HH * STR * (int)sizeof(float);  // 69632
    cudaFuncSetAttribute(attn_kernel,
                         cudaFuncAttributeMaxDynamicSharedMemorySize, smem_bytes);
    dim3 grid(TT/BQ, BB);
    attn_kernel<<<grid, 256, smem_bytes>>>(out);
}

// round 2
// speedup vs baseline: 2.6906x; 2.6906x over previous
#include <cuda_runtime.h>
#include <math.h>

#define BB 16
#define TT 2048
#define CC 68
#define HH 64
#define BT (BB*TT)
#define BQ 128           // q rows per CTA
#define BK 64            // k rows per tile
#define STR 68           // smem row stride (floats)
#define NKT (TT/BK)

// Projected Q (pre-scaled, tf32-rounded), K, V (tf32-rounded): 3 x 8 MB.
__device__ float g_Q[BT*HH];
__device__ float g_K[BT*HH];
__device__ float g_V[BT*HH];

__device__ __forceinline__ float to_tf32(float x) {
    unsigned u;
    asm("cvt.rna.tf32.f32 %0, %1;" : "=r"(u) : "f"(x));
    return __uint_as_float(u);
}
__device__ __forceinline__ unsigned tf32_bits(float x) {
    unsigned u;
    asm("cvt.rna.tf32.f32 %0, %1;" : "=r"(u) : "f"(x));
    return u;
}

// D += A * B  (m16n8k8, tf32 inputs, fp32 accumulate)
__device__ __forceinline__ void mma_tf32(float d[4],
                                         const unsigned a[4],
                                         unsigned b0, unsigned b1) {
    asm volatile(
        "mma.sync.aligned.m16n8k8.row.col.f32.tf32.tf32.f32 "
        "{%0,%1,%2,%3}, {%4,%5,%6,%7}, {%8,%9}, {%0,%1,%2,%3};"
        : "+f"(d[0]), "+f"(d[1]), "+f"(d[2]), "+f"(d[3])
        : "r"(a[0]), "r"(a[1]), "r"(a[2]), "r"(a[3]),
          "r"(b0), "r"(b1));
}

// ---------------------------------------------------------------------------
// Kernel 1: fused QKV projection (fp32 math, tf32-rounded outputs).
// ---------------------------------------------------------------------------
__global__ __launch_bounds__(256) void proj_kernel(
    const float* __restrict__ x,
    const float* __restrict__ Wk,
    const float* __restrict__ Wq,
    const float* __restrict__ Wv)
{
    __shared__ float sx[16][CC];
    const int row0 = blockIdx.x * 16;
    const int tid  = threadIdx.x;

    for (int i = tid; i < 16*CC; i += 256)
        sx[i / CC][i % CC] = x[row0*CC + i];
    __syncthreads();

    const int h  = tid & 63;
    const int rg = tid >> 6;

    float ak[4] = {0.f,0.f,0.f,0.f};
    float aq[4] = {0.f,0.f,0.f,0.f};
    float av[4] = {0.f,0.f,0.f,0.f};

    #pragma unroll 4
    for (int c = 0; c < CC; c++) {
        const float wk = Wk[c*HH + h];
        const float wq = Wq[c*HH + h];
        const float wv = Wv[c*HH + h];
        #pragma unroll
        for (int d = 0; d < 4; d++) {
            const float xv = sx[rg*4 + d][c];
            ak[d] = fmaf(xv, wk, ak[d]);
            aq[d] = fmaf(xv, wq, aq[d]);
            av[d] = fmaf(xv, wv, av[d]);
        }
    }

    #pragma unroll
    for (int d = 0; d < 4; d++) {
        const int row = row0 + rg*4 + d;
        g_K[row*HH + h] = to_tf32(ak[d]);
        g_Q[row*HH + h] = to_tf32(aq[d] * 0.125f);  // fold 1/sqrt(64) into Q
        g_V[row*HH + h] = to_tf32(av[d]);
    }
}

// ---------------------------------------------------------------------------
// Kernel 2: flash attention on tensor cores (tf32 mma.sync, fp32 accum).
// CTA = 128 q rows x 64 head. 8 warps; warp w owns rows [w*16, w*16+16).
// ---------------------------------------------------------------------------
__global__ __launch_bounds__(256, 2) void attn_kernel(float* __restrict__ out)
{
    extern __shared__ float sm[];
    float* sK = sm;                  // [64][STR]  K tile, [j][c]
    float* sV = sm + BK*STR;         // [64][STR]  V tile, [j][h]
    float* sP = sm + 2*BK*STR;       // [128][STR] P tile (also Q staging)

    const int b   = blockIdx.y;
    const int qt  = blockIdx.x;
    const int tid = threadIdx.x;
    const int wid = tid >> 5;
    const int lane = tid & 31;
    const int lr  = lane >> 2;       // 0..7 row-in-group
    const int la3 = lane & 3;        // 0..3
    const int wrow0 = wid * 16;      // warp's row base within CTA tile

    const float* Qb = g_Q + (size_t)(b*TT + qt*BQ)*HH;
    const float* Kb = g_K + (size_t)b*TT*HH;
    const float* Vb = g_V + (size_t)b*TT*HH;

    // ---- stage Q into sP (coalesced), then extract A fragments ----
    for (int idx = tid; idx < BQ*(HH/4); idx += 256) {
        const int row = idx >> 4, c4 = idx & 15;
        *(float4*)(sP + row*STR + c4*4) = *(const float4*)(Qb + row*HH + c4*4);
    }
    __syncthreads();

    unsigned qa[8][4];   // Q A-fragments: 8 k-steps x 4 regs
    #pragma unroll
    for (int k = 0; k < 8; k++) {
        const int c0 = k*8 + la3;
        qa[k][0] = __float_as_uint(sP[(wrow0 + lr    )*STR + c0    ]);
        qa[k][1] = __float_as_uint(sP[(wrow0 + lr + 8)*STR + c0    ]);
        qa[k][2] = __float_as_uint(sP[(wrow0 + lr    )*STR + c0 + 4]);
        qa[k][3] = __float_as_uint(sP[(wrow0 + lr + 8)*STR + c0 + 4]);
    }

    float m0 = -INFINITY, m1 = -INFINITY, l0 = 0.f, l1 = 0.f;
    float o[8][4];
    #pragma unroll
    for (int nt = 0; nt < 8; nt++)
        #pragma unroll
        for (int r = 0; r < 4; r++) o[nt][r] = 0.f;

    for (int kt = 0; kt < NKT; kt++) {
        __syncthreads();   // prev PV reads of sK/sV/sP done; Q frags extracted
        {
            const float* Kt = Kb + (size_t)kt*BK*HH;
            const float* Vt = Vb + (size_t)kt*BK*HH;
            for (int idx = tid; idx < BK*(HH/4); idx += 256) {
                const int j = idx >> 4, c4 = idx & 15;
                *(float4*)(sK + j*STR + c4*4) = *(const float4*)(Kt + j*HH + c4*4);
                *(float4*)(sV + j*STR + c4*4) = *(const float4*)(Vt + j*HH + c4*4);
            }
        }
        __syncthreads();

        // ---- S = Q K^T via tensor cores ----
        float s[8][4];
        #pragma unroll
        for (int nt = 0; nt < 8; nt++)
            #pragma unroll
            for (int r = 0; r < 4; r++) s[nt][r] = 0.f;

        #pragma unroll
        for (int k = 0; k < 8; k++) {
            #pragma unroll
            for (int nt = 0; nt < 8; nt++) {
                // B(k-dim=c, n-dim=j): b = K[j][c]
                const int j = nt*8 + lr;
                const int c = k*8 + la3;
                const unsigned b0 = __float_as_uint(sK[j*STR + c    ]);
                const unsigned b1 = __float_as_uint(sK[j*STR + c + 4]);
                mma_tf32(s[nt], qa[k], b0, b1);
            }
        }

        // ---- online softmax (rows lr and lr+8; quad = 4 lanes share a row) ----
        float rm0 = s[0][0], rm1 = s[0][2];
        #pragma unroll
        for (int nt = 0; nt < 8; nt++) {
            rm0 = fmaxf(rm0, fmaxf(s[nt][0], s[nt][1]));
            rm1 = fmaxf(rm1, fmaxf(s[nt][2], s[nt][3]));
        }
        rm0 = fmaxf(rm0, __shfl_xor_sync(0xffffffffu, rm0, 1));
        rm0 = fmaxf(rm0, __shfl_xor_sync(0xffffffffu, rm0, 2));
        rm1 = fmaxf(rm1, __shfl_xor_sync(0xffffffffu, rm1, 1));
        rm1 = fmaxf(rm1, __shfl_xor_sync(0xffffffffu, rm1, 2));

        const float mn0 = fmaxf(m0, rm0);
        const float mn1 = fmaxf(m1, rm1);
        const float a0 = __expf(m0 - mn0);
        const float a1 = __expf(m1 - mn1);
        m0 = mn0; m1 = mn1;

        float rs0 = 0.f, rs1 = 0.f;
        #pragma unroll
        for (int nt = 0; nt < 8; nt++) {
            s[nt][0] = __expf(s[nt][0] - mn0);
            s[nt][1] = __expf(s[nt][1] - mn0);
            s[nt][2] = __expf(s[nt][2] - mn1);
            s[nt][3] = __expf(s[nt][3] - mn1);
            rs0 += s[nt][0] + s[nt][1];
            rs1 += s[nt][2] + s[nt][3];
        }
        rs0 += __shfl_xor_sync(0xffffffffu, rs0, 1);
        rs0 += __shfl_xor_sync(0xffffffffu, rs0, 2);
        rs1 += __shfl_xor_sync(0xffffffffu, rs1, 1);
        rs1 += __shfl_xor_sync(0xffffffffu, rs1, 2);

        l0 = l0*a0 + rs0;
        l1 = l1*a1 + rs1;
        #pragma unroll
        for (int nt = 0; nt < 8; nt++) {
            o[nt][0] *= a0; o[nt][1] *= a0;
            o[nt][2] *= a1; o[nt][3] *= a1;
        }

        // ---- P (tf32-rounded) -> sP, acc layout, STS.64 pairs ----
        #pragma unroll
        for (int nt = 0; nt < 8; nt++) {
            const int col = nt*8 + 2*la3;
            float2 p0 = make_float2(__uint_as_float(tf32_bits(s[nt][0])),
                                    __uint_as_float(tf32_bits(s[nt][1])));
            float2 p1 = make_float2(__uint_as_float(tf32_bits(s[nt][2])),
                                    __uint_as_float(tf32_bits(s[nt][3])));
            *(float2*)(sP + (wrow0 + lr    )*STR + col) = p0;
            *(float2*)(sP + (wrow0 + lr + 8)*STR + col) = p1;
        }
        __syncthreads();

        // ---- O += P V via tensor cores ----
        #pragma unroll
        for (int k = 0; k < 8; k++) {
            unsigned pa[4];
            const int c0 = k*8 + la3;
            pa[0] = __float_as_uint(sP[(wrow0 + lr    )*STR + c0    ]);
            pa[1] = __float_as_uint(sP[(wrow0 + lr + 8)*STR + c0    ]);
            pa[2] = __float_as_uint(sP[(wrow0 + lr    )*STR + c0 + 4]);
            pa[3] = __float_as_uint(sP[(wrow0 + lr + 8)*STR + c0 + 4]);
            #pragma unroll
            for (int nt = 0; nt < 8; nt++) {
                // B(k-dim=j, n-dim=h): b = V[j][h]
                const int j = k*8 + la3;
                const int h = nt*8 + lr;
                const unsigned b0 = __float_as_uint(sV[(j    )*STR + h]);
                const unsigned b1 = __float_as_uint(sV[(j + 4)*STR + h]);
                mma_tf32(o[nt], pa, b0, b1);
            }
        }
    }

    // ---- epilogue: O / l ----
    const float inv0 = 1.f / l0;
    const float inv1 = 1.f / l1;
    float* Ob = out + (size_t)(b*TT + qt*BQ)*HH;
    #pragma unroll
    for (int nt = 0; nt < 8; nt++) {
        const int col = nt*8 + 2*la3;
        float2 r0 = make_float2(o[nt][0]*inv0, o[nt][1]*inv0);
        float2 r1 = make_float2(o[nt][2]*inv1, o[nt][3]*inv1);
        *(float2*)(Ob + (wrow0 + lr    )*HH + col) = r0;
        *(float2*)(Ob + (wrow0 + lr + 8)*HH + col) = r1;
    }
}

// ---------------------------------------------------------------------------
extern "C" void kernel_launch(void* const* d_in, const int* in_sizes, int n_in,
                              void* d_out, int out_size)
{
    const float* x  = (const float*)d_in[0];
    const float* Wk = (const float*)d_in[1];
    const float* Wq = (const float*)d_in[2];
    const float* Wv = (const float*)d_in[3];
    float* out = (float*)d_out;

    proj_kernel<<<BT/16, 256>>>(x, Wk, Wq, Wv);

    const int smem_bytes = (2*BK + BQ) * STR * (int)sizeof(float);  // 69632
    cudaFuncSetAttribute(attn_kernel,
                         cudaFuncAttributeMaxDynamicSharedMemorySize, smem_bytes);
    dim3 grid(TT/BQ, BB);
    attn_kernel<<<grid, 256, smem_bytes>>>(out);
}

// round 4
// speedup vs baseline: 4.3818x; 1.6286x over previous
#include <cuda_runtime.h>
#include <cstdint>
#include <math.h>

#define BB 16
#define TT 2048
#define CC 68
#define HH 64
#define BT (BB*TT)
#define BQ 128
#define BK 64
#define NKT (TT/BK)     // 32
#define STR 68          // smem row stride in floats

// Projected Q (pre-scaled by log2e/8, tf32-rounded), K, V (tf32-rounded).
__device__ float g_Q[BT*HH];
__device__ float g_K[BT*HH];
__device__ float g_V[BT*HH];

// ---- smem layout (float offsets) ----
#define OFF_Q   0
#define OFF_K0  (BQ*STR)                 // 8704
#define OFF_V0  (OFF_K0 + BK*STR)
#define OFF_K1  (OFF_V0 + BK*STR)
#define OFF_V1  (OFF_K1 + BK*STR)
#define SM_FLOATS (OFF_V1 + BK*STR)      // 26112
#define SM_BYTES  (SM_FLOATS*4)          // 104448 -> 2 CTAs/SM

__device__ __forceinline__ uint32_t smem_u32(const void* p) {
    uint32_t a;
    asm("{ .reg .u64 t; cvta.to.shared.u64 t, %1; cvt.u32.u64 %0, t; }" : "=r"(a) : "l"(p));
    return a;
}
__device__ __forceinline__ void cpa16(uint32_t dst, const void* src) {
    asm volatile("cp.async.cg.shared.global [%0], [%1], 16;" :: "r"(dst), "l"(src) : "memory");
}
__device__ __forceinline__ void cpa_commit() {
    asm volatile("cp.async.commit_group;" ::: "memory");
}
__device__ __forceinline__ uint32_t frna(float x) {
    uint32_t u; asm("cvt.rna.tf32.f32 %0, %1;" : "=r"(u) : "f"(x)); return u;
}
__device__ __forceinline__ float ex2(float x) {
    float r; asm("ex2.approx.f32 %0, %1;" : "=f"(r) : "f"(x)); return r;
}
// D += A*B, m16n8k8 tf32 (fp32 accum). a/b passed as fp32 regs; HW truncates to tf32.
__device__ __forceinline__ void mma4(float d[4],
                                     float a0, float a1, float a2, float a3,
                                     float b0, float b1) {
    asm volatile(
        "mma.sync.aligned.m16n8k8.row.col.f32.tf32.tf32.f32 "
        "{%0,%1,%2,%3}, {%4,%5,%6,%7}, {%8,%9}, {%0,%1,%2,%3};"
        : "+f"(d[0]), "+f"(d[1]), "+f"(d[2]), "+f"(d[3])
        : "r"(__float_as_uint(a0)), "r"(__float_as_uint(a1)),
          "r"(__float_as_uint(a2)), "r"(__float_as_uint(a3)),
          "r"(__float_as_uint(b0)), "r"(__float_as_uint(b1)));
}

// ---------------------------------------------------------------------------
// Kernel 1: fused QKV projection. Q pre-scaled by log2(e)/8 (exp -> ex2).
// ---------------------------------------------------------------------------
__global__ __launch_bounds__(256) void proj_kernel(
    const float* __restrict__ x,
    const float* __restrict__ Wk,
    const float* __restrict__ Wq,
    const float* __restrict__ Wv)
{
    __shared__ float sx[16][CC];
    const int row0 = blockIdx.x * 16;
    const int tid  = threadIdx.x;

    for (int i = tid; i < 16*CC; i += 256)
        sx[i / CC][i % CC] = x[row0*CC + i];
    __syncthreads();

    const int h  = tid & 63;
    const int rg = tid >> 6;

    float ak[4] = {0.f,0.f,0.f,0.f};
    float aq[4] = {0.f,0.f,0.f,0.f};
    float av[4] = {0.f,0.f,0.f,0.f};

    #pragma unroll 4
    for (int c = 0; c < CC; c++) {
        const float wk = Wk[c*HH + h];
        const float wq = Wq[c*HH + h];
        const float wv = Wv[c*HH + h];
        #pragma unroll
        for (int d = 0; d < 4; d++) {
            const float xv = sx[rg*4 + d][c];
            ak[d] = fmaf(xv, wk, ak[d]);
            aq[d] = fmaf(xv, wq, aq[d]);
            av[d] = fmaf(xv, wv, av[d]);
        }
    }

    const float qscale = 0.125f * 1.4426950408889634f;  // (1/sqrt(64)) * log2(e)
    #pragma unroll
    for (int d = 0; d < 4; d++) {
        const int row = row0 + rg*4 + d;
        g_K[row*HH + h] = __uint_as_float(frna(ak[d]));
        g_Q[row*HH + h] = __uint_as_float(frna(aq[d] * qscale));
        g_V[row*HH + h] = __uint_as_float(frna(av[d]));
    }
}

// ---------------------------------------------------------------------------
// Kernel 2: flash attention, tf32 mma.sync, 4 warps x m32, no P smem trip.
// ---------------------------------------------------------------------------
__global__ __launch_bounds__(128, 2) void attn_kernel(float* __restrict__ out)
{
    extern __shared__ float sm[];
    const uint32_t sb = smem_u32(sm);

    const int b    = blockIdx.y;
    const int qt   = blockIdx.x;
    const int tid  = threadIdx.x;
    const int wid  = tid >> 5;
    const int lane = tid & 31;
    const int lr   = lane >> 2;      // 0..7
    const int la3  = lane & 3;       // 0..3
    const int wr0  = wid * 32;       // warp row base (m32 per warp)

    const float* Qb = g_Q + (size_t)(b*TT + qt*BQ)*HH;
    const float* Kb = g_K + (size_t)b*TT*HH;
    const float* Vb = g_V + (size_t)b*TT*HH;

    // ---- prologue: stage Q (group0), KV0 (group1), KV1 (group2) ----
    #pragma unroll
    for (int i = 0; i < 16; i++) {
        const int g = tid + i*128, row = g >> 4, ch = g & 15;
        cpa16(sb + (uint32_t)(OFF_Q + row*STR)*4u + (uint32_t)ch*16u,
              Qb + row*HH + ch*4);
    }
    cpa_commit();
    #pragma unroll
    for (int st = 0; st < 2; st++) {
        const float* Ks = Kb + (size_t)st*BK*HH;
        const float* Vs = Vb + (size_t)st*BK*HH;
        const uint32_t ko = (st ? OFF_K1 : OFF_K0), vo = (st ? OFF_V1 : OFF_V0);
        #pragma unroll
        for (int i = 0; i < 8; i++) {
            const int g = tid + i*128, row = g >> 4, ch = g & 15;
            cpa16(sb + (ko + (uint32_t)row*STR)*4u + (uint32_t)ch*16u, Ks + row*HH + ch*4);
            cpa16(sb + (vo + (uint32_t)row*STR)*4u + (uint32_t)ch*16u, Vs + row*HH + ch*4);
        }
        cpa_commit();
    }

    asm volatile("cp.async.wait_group 2;" ::: "memory");   // Q ready
    __syncthreads();

    // ---- extract Q A-fragments for the warp's 32 rows (2 m16 blocks) ----
    float qa[8][8];
    #pragma unroll
    for (int k = 0; k < 8; k++) {
        const int c0 = k*8 + la3;
        qa[k][0] = sm[OFF_Q + (wr0 + lr      )*STR + c0    ];
        qa[k][1] = sm[OFF_Q + (wr0 + lr +  8 )*STR + c0    ];
        qa[k][2] = sm[OFF_Q + (wr0 + lr      )*STR + c0 + 4];
        qa[k][3] = sm[OFF_Q + (wr0 + lr +  8 )*STR + c0 + 4];
        qa[k][4] = sm[OFF_Q + (wr0 + lr + 16 )*STR + c0    ];
        qa[k][5] = sm[OFF_Q + (wr0 + lr + 24 )*STR + c0    ];
        qa[k][6] = sm[OFF_Q + (wr0 + lr + 16 )*STR + c0 + 4];
        qa[k][7] = sm[OFF_Q + (wr0 + lr + 24 )*STR + c0 + 4];
    }

    float oA[8][4], oB[8][4];
    #pragma unroll
    for (int nt = 0; nt < 8; nt++)
        #pragma unroll
        for (int r = 0; r < 4; r++) { oA[nt][r] = 0.f; oB[nt][r] = 0.f; }
    float lA0 = 0.f, lA1 = 0.f, lB0 = 0.f, lB1 = 0.f;

    for (int t = 0; t < NKT; t++) {
        // prefetch KV(t+1) into stage (t+1)&1 (freed at end of t-1)
        if (t >= 1 && t + 1 < NKT) {
            const float* Ks = Kb + (size_t)(t+1)*BK*HH;
            const float* Vs = Vb + (size_t)(t+1)*BK*HH;
            const uint32_t ko = ((t+1)&1 ? OFF_K1 : OFF_K0);
            const uint32_t vo = ((t+1)&1 ? OFF_V1 : OFF_V0);
            #pragma unroll
            for (int i = 0; i < 8; i++) {
                const int g = tid + i*128, row = g >> 4, ch = g & 15;
                cpa16(sb + (ko + (uint32_t)row*STR)*4u + (uint32_t)ch*16u, Ks + row*HH + ch*4);
                cpa16(sb + (vo + (uint32_t)row*STR)*4u + (uint32_t)ch*16u, Vs + row*HH + ch*4);
            }
            cpa_commit();
        }
        if (t + 1 < NKT) asm volatile("cp.async.wait_group 1;" ::: "memory");
        else             asm volatile("cp.async.wait_group 0;" ::: "memory");
        __syncthreads();

        const float* kp = sm + ((t&1) ? OFF_K1 : OFF_K0);
        const float* vp = sm + ((t&1) ? OFF_V1 : OFF_V0);

        // ---- S = Q K^T ----
        float sA[8][4], sB[8][4];
        #pragma unroll
        for (int nt = 0; nt < 8; nt++)
            #pragma unroll
            for (int r = 0; r < 4; r++) { sA[nt][r] = 0.f; sB[nt][r] = 0.f; }

        #pragma unroll
        for (int k = 0; k < 8; k++) {
            const int c0 = k*8 + la3;
            #pragma unroll
            for (int nt = 0; nt < 8; nt++) {
                const int j = nt*8 + lr;
                const float b0 = kp[j*STR + c0];
                const float b1 = kp[j*STR + c0 + 4];
                mma4(sA[nt], qa[k][0], qa[k][1], qa[k][2], qa[k][3], b0, b1);
                mma4(sB[nt], qa[k][4], qa[k][5], qa[k][6], qa[k][7], b0, b1);
            }
        }

        // ---- P = exp2(S) (tf32-rounded for numerator/denominator consistency) ----
        float rs0 = 0.f, rs1 = 0.f, rs2 = 0.f, rs3 = 0.f;
        #pragma unroll
        for (int nt = 0; nt < 8; nt++) {
            sA[nt][0] = __uint_as_float(frna(ex2(sA[nt][0])));
            sA[nt][1] = __uint_as_float(frna(ex2(sA[nt][1])));
            sA[nt][2] = __uint_as_float(frna(ex2(sA[nt][2])));
            sA[nt][3] = __uint_as_float(frna(ex2(sA[nt][3])));
            sB[nt][0] = __uint_as_float(frna(ex2(sB[nt][0])));
            sB[nt][1] = __uint_as_float(frna(ex2(sB[nt][1])));
            sB[nt][2] = __uint_as_float(frna(ex2(sB[nt][2])));
            sB[nt][3] = __uint_as_float(frna(ex2(sB[nt][3])));
            rs0 += sA[nt][0] + sA[nt][1];
            rs1 += sA[nt][2] + sA[nt][3];
            rs2 += sB[nt][0] + sB[nt][1];
            rs3 += sB[nt][2] + sB[nt][3];
        }
        lA0 += rs0; lA1 += rs1; lB0 += rs2; lB1 += rs3;

        // ---- O += P V.  Accumulator-as-A-fragment: a = {c0,c2,c1,c3},
        //      V rows permuted to match: b0 = V[kk*8+2*la3], b1 = V[kk*8+2*la3+1].
        #pragma unroll
        for (int kk = 0; kk < 8; kk++) {
            const int j0 = kk*8 + 2*la3;
            #pragma unroll
            for (int nt = 0; nt < 8; nt++) {
                const int h = nt*8 + lr;
                const float b0 = vp[(j0    )*STR + h];
                const float b1 = vp[(j0 + 1)*STR + h];
                mma4(oA[nt], sA[kk][0], sA[kk][2], sA[kk][1], sA[kk][3], b0, b1);
                mma4(oB[nt], sB[kk][0], sB[kk][2], sB[kk][1], sB[kk][3], b0, b1);
            }
        }
        __syncthreads();   // all warps done with stage t&1 before next prefetch
    }

    // ---- row-sum quad reduction + epilogue ----
    lA0 += __shfl_xor_sync(0xffffffffu, lA0, 1);
    lA0 += __shfl_xor_sync(0xffffffffu, lA0, 2);
    lA1 += __shfl_xor_sync(0xffffffffu, lA1, 1);
    lA1 += __shfl_xor_sync(0xffffffffu, lA1, 2);
    lB0 += __shfl_xor_sync(0xffffffffu, lB0, 1);
    lB0 += __shfl_xor_sync(0xffffffffu, lB0, 2);
    lB1 += __shfl_xor_sync(0xffffffffu, lB1, 1);
    lB1 += __shfl_xor_sync(0xffffffffu, lB1, 2);
    const float iA0 = 1.f / lA0, iA1 = 1.f / lA1;
    const float iB0 = 1.f / lB0, iB1 = 1.f / lB1;

    float* Ob = out + (size_t)(b*TT + qt*BQ)*HH;
    #pragma unroll
    for (int nt = 0; nt < 8; nt++) {
        const int col = nt*8 + 2*la3;
        *(float2*)(Ob + (wr0 + lr      )*HH + col) = make_float2(oA[nt][0]*iA0, oA[nt][1]*iA0);
        *(float2*)(Ob + (wr0 + lr +  8 )*HH + col) = make_float2(oA[nt][2]*iA1, oA[nt][3]*iA1);
        *(float2*)(Ob + (wr0 + lr + 16 )*HH + col) = make_float2(oB[nt][0]*iB0, oB[nt][1]*iB0);
        *(float2*)(Ob + (wr0 + lr + 24 )*HH + col) = make_float2(oB[nt][2]*iB1, oB[nt][3]*iB1);
    }
}

// ---------------------------------------------------------------------------
extern "C" void kernel_launch(void* const* d_in, const int* in_sizes, int n_in,
                              void* d_out, int out_size)
{
    const float* x  = (const float*)d_in[0];
    const float* Wk = (const float*)d_in[1];
    const float* Wq = (const float*)d_in[2];
    const float* Wv = (const float*)d_in[3];
    float* out = (float*)d_out;

    proj_kernel<<<BT/16, 256>>>(x, Wk, Wq, Wv);

    cudaFuncSetAttribute(attn_kernel,
                         cudaFuncAttributeMaxDynamicSharedMemorySize, SM_BYTES);
    dim3 grid(TT/BQ, BB);
    attn_kernel<<<grid, 128, SM_BYTES>>>(out);
}

// round 5
// speedup vs baseline: 7.2446x; 1.6533x over previous
#include <cuda_runtime.h>
#include <cuda_fp16.h>
#include <cstdint>
#include <math.h>

#define BB 16
#define TT 2048
#define CC 68
#define HH 64
#define BT (BB*TT)
#define BQ 128
#define BK 64
#define NKT (TT/BK)     // 32
#define RS  72          // smem row stride in halves (36 words -> conflict-free)

// fp16 scratch: Q (pre-scaled by log2e/8), K row-major [t][h]; V transposed [b][h][t].
__device__ __align__(16) __half g_Q[BT*HH];
__device__ __align__(16) __half g_K[BT*HH];
__device__ __align__(16) __half g_Vt[BB*HH*TT];

// ---- smem layout (half offsets) ----
#define OFF_Q   0
#define OFF_K0  (BQ*RS)                  // 9216
#define OFF_V0  (OFF_K0 + BK*RS)
#define OFF_K1  (OFF_V0 + BK*RS)
#define OFF_V1  (OFF_K1 + BK*RS)
#define SM_HALVES (OFF_V1 + BK*RS)       // 27648
#define SM_BYTES  (SM_HALVES*2)          // 55296

__device__ __forceinline__ uint32_t smem_u32(const void* p) {
    uint32_t a;
    asm("{ .reg .u64 t; cvta.to.shared.u64 t, %1; cvt.u32.u64 %0, t; }" : "=r"(a) : "l"(p));
    return a;
}
__device__ __forceinline__ void cpa16(uint32_t dst, const void* src) {
    asm volatile("cp.async.cg.shared.global [%0], [%1], 16;" :: "r"(dst), "l"(src) : "memory");
}
__device__ __forceinline__ void cpa_commit() {
    asm volatile("cp.async.commit_group;" ::: "memory");
}
__device__ __forceinline__ float ex2(float x) {
    float r; asm("ex2.approx.f32 %0, %1;" : "=f"(r) : "f"(x)); return r;
}
// pack {lo=x, hi=y} into f16x2
__device__ __forceinline__ uint32_t pack_h2(float x, float y) {
    uint32_t r; asm("cvt.rn.f16x2.f32 %0, %1, %2;" : "=r"(r) : "f"(y), "f"(x)); return r;
}
__device__ __forceinline__ uint32_t lds_b32(const __half* p) {
    return *(const uint32_t*)p;
}
// D += A*B, m16n8k16 f16 inputs, f32 accumulate
__device__ __forceinline__ void mma_f16(float d[4],
                                        uint32_t a0, uint32_t a1, uint32_t a2, uint32_t a3,
                                        uint32_t b0, uint32_t b1) {
    asm volatile(
        "mma.sync.aligned.m16n8k16.row.col.f32.f16.f16.f32 "
        "{%0,%1,%2,%3}, {%4,%5,%6,%7}, {%8,%9}, {%0,%1,%2,%3};"
        : "+f"(d[0]), "+f"(d[1]), "+f"(d[2]), "+f"(d[3])
        : "r"(a0), "r"(a1), "r"(a2), "r"(a3), "r"(b0), "r"(b1));
}

// ---------------------------------------------------------------------------
// Kernel 1: fused QKV projection, fp16 outputs; V written transposed [b][h][t].
// 32 x-rows per block, 256 threads; thread (rg,h) computes 8 rows for column h.
// ---------------------------------------------------------------------------
__global__ __launch_bounds__(256) void proj_kernel(
    const float* __restrict__ x,
    const float* __restrict__ Wk,
    const float* __restrict__ Wq,
    const float* __restrict__ Wv)
{
    __shared__ float sx[32][CC];
    __shared__ float sv[64][33];
    const int row0 = blockIdx.x * 32;
    const int tid  = threadIdx.x;

    for (int i = tid; i < 32*CC; i += 256)
        sx[i / CC][i % CC] = x[row0*CC + i];
    __syncthreads();

    const int h  = tid & 63;
    const int rg = tid >> 6;          // 0..3, 8 rows each

    float ak[8], aq[8], av[8];
    #pragma unroll
    for (int d = 0; d < 8; d++) { ak[d] = 0.f; aq[d] = 0.f; av[d] = 0.f; }

    #pragma unroll 4
    for (int c = 0; c < CC; c++) {
        const float wk = Wk[c*HH + h];
        const float wq = Wq[c*HH + h];
        const float wv = Wv[c*HH + h];
        #pragma unroll
        for (int d = 0; d < 8; d++) {
            const float xv = sx[rg*8 + d][c];
            ak[d] = fmaf(xv, wk, ak[d]);
            aq[d] = fmaf(xv, wq, aq[d]);
            av[d] = fmaf(xv, wv, av[d]);
        }
    }

    const float qscale = 0.125f * 1.4426950408889634f;  // (1/sqrt(64))*log2(e)
    #pragma unroll
    for (int d = 0; d < 8; d++) {
        const int row = row0 + rg*8 + d;
        g_K[row*HH + h] = __float2half_rn(ak[d]);
        g_Q[row*HH + h] = __float2half_rn(aq[d] * qscale);
        sv[h][rg*8 + d] = av[d];
    }
    __syncthreads();

    // transpose V out: [b][h][t], 8 consecutive t per thread (16B store)
    const int b  = row0 >> 11;        // row0 / TT
    const int t0 = row0 & (TT-1);
    const int h2 = tid >> 2;
    const int c4 = tid & 3;
    __half tmp[8];
    #pragma unroll
    for (int j = 0; j < 8; j++) tmp[j] = __float2half_rn(sv[h2][c4*8 + j]);
    *(uint4*)(g_Vt + ((size_t)b*HH + h2)*TT + t0 + c4*8) = *(uint4*)tmp;
}

// ---------------------------------------------------------------------------
// Kernel 2: flash attention, fp16 m16n8k16 mma.sync, 4 warps x m32.
// P never touches smem (accumulator->A-fragment identity).
// ---------------------------------------------------------------------------
__global__ __launch_bounds__(128, 2) void attn_kernel(float* __restrict__ out)
{
    extern __shared__ __half sm[];
    const uint32_t sb = smem_u32(sm);

    const int b    = blockIdx.y;
    const int qt   = blockIdx.x;
    const int tid  = threadIdx.x;
    const int wid  = tid >> 5;
    const int lane = tid & 31;
    const int lr   = lane >> 2;      // 0..7
    const int la3  = lane & 3;       // 0..3
    const int wr0  = wid * 32;       // warp row base (m32)

    const __half* Qb  = g_Q  + (size_t)(b*TT + qt*BQ)*HH;
    const __half* Kb  = g_K  + (size_t)b*TT*HH;
    const __half* Vtb = g_Vt + (size_t)b*HH*TT;

    // ---- prologue: Q (group0), KV0 (group1), KV1 (group2) ----
    #pragma unroll
    for (int i = 0; i < 8; i++) {                 // Q: 128 rows x 8 chunks
        const int g = tid + i*128, row = g >> 3, ch = g & 7;
        cpa16(sb + (uint32_t)(OFF_Q + row*RS + ch*8)*2u, Qb + row*HH + ch*8);
    }
    cpa_commit();
    #pragma unroll
    for (int st = 0; st < 2; st++) {
        const __half* Ks = Kb + (size_t)st*BK*HH;
        const __half* Vs = Vtb + st*BK;
        const uint32_t ko = (st ? OFF_K1 : OFF_K0), vo = (st ? OFF_V1 : OFF_V0);
        #pragma unroll
        for (int i = 0; i < 4; i++) {             // 64 rows x 8 chunks = 512
            const int g = tid + i*128, row = g >> 3, ch = g & 7;
            cpa16(sb + (ko + (uint32_t)(row*RS + ch*8))*2u, Ks + row*HH + ch*8);
            cpa16(sb + (vo + (uint32_t)(row*RS + ch*8))*2u, Vs + (size_t)row*TT + ch*8);
        }
        cpa_commit();
    }

    asm volatile("cp.async.wait_group 2;" ::: "memory");   // Q ready
    __syncthreads();

    // ---- Q A-fragments: 4 k-steps x 8 regs (two m16 blocks) ----
    uint32_t qa[4][8];
    #pragma unroll
    for (int k = 0; k < 4; k++) {
        const int c0 = k*16 + 2*la3;
        const __half* q0 = sm + OFF_Q + c0;
        qa[k][0] = lds_b32(q0 + (wr0 + lr      )*RS    );
        qa[k][1] = lds_b32(q0 + (wr0 + lr +  8 )*RS    );
        qa[k][2] = lds_b32(q0 + (wr0 + lr      )*RS + 8);
        qa[k][3] = lds_b32(q0 + (wr0 + lr +  8 )*RS + 8);
        qa[k][4] = lds_b32(q0 + (wr0 + lr + 16 )*RS    );
        qa[k][5] = lds_b32(q0 + (wr0 + lr + 24 )*RS    );
        qa[k][6] = lds_b32(q0 + (wr0 + lr + 16 )*RS + 8);
        qa[k][7] = lds_b32(q0 + (wr0 + lr + 24 )*RS + 8);
    }

    float oA[8][4], oB[8][4];
    #pragma unroll
    for (int nt = 0; nt < 8; nt++)
        #pragma unroll
        for (int r = 0; r < 4; r++) { oA[nt][r] = 0.f; oB[nt][r] = 0.f; }
    float lA0 = 0.f, lA1 = 0.f, lB0 = 0.f, lB1 = 0.f;

    for (int t = 0; t < NKT; t++) {
        if (t >= 1 && t + 1 < NKT) {
            const __half* Ks = Kb + (size_t)(t+1)*BK*HH;
            const __half* Vs = Vtb + (t+1)*BK;
            const uint32_t ko = ((t+1)&1 ? OFF_K1 : OFF_K0);
            const uint32_t vo = ((t+1)&1 ? OFF_V1 : OFF_V0);
            #pragma unroll
            for (int i = 0; i < 4; i++) {
                const int g = tid + i*128, row = g >> 3, ch = g & 7;
                cpa16(sb + (ko + (uint32_t)(row*RS + ch*8))*2u, Ks + row*HH + ch*8);
                cpa16(sb + (vo + (uint32_t)(row*RS + ch*8))*2u, Vs + (size_t)row*TT + ch*8);
            }
            cpa_commit();
        }
        if (t + 1 < NKT) asm volatile("cp.async.wait_group 1;" ::: "memory");
        else             asm volatile("cp.async.wait_group 0;" ::: "memory");
        __syncthreads();

        const __half* kp = sm + ((t&1) ? OFF_K1 : OFF_K0);
        const __half* vp = sm + ((t&1) ? OFF_V1 : OFF_V0);

        // ---- S = Q K^T ----
        float sA[8][4], sB[8][4];
        #pragma unroll
        for (int nt = 0; nt < 8; nt++)
            #pragma unroll
            for (int r = 0; r < 4; r++) { sA[nt][r] = 0.f; sB[nt][r] = 0.f; }

        #pragma unroll
        for (int k = 0; k < 4; k++) {
            const int c0 = k*16 + 2*la3;
            #pragma unroll
            for (int nt = 0; nt < 8; nt++) {
                const __half* kr = kp + (nt*8 + lr)*RS + c0;
                const uint32_t b0 = lds_b32(kr);
                const uint32_t b1 = lds_b32(kr + 8);
                mma_f16(sA[nt], qa[k][0], qa[k][1], qa[k][2], qa[k][3], b0, b1);
                mma_f16(sB[nt], qa[k][4], qa[k][5], qa[k][6], qa[k][7], b0, b1);
            }
        }

        // ---- P = exp2(S); row sums (fp32); pack to f16x2 A-fragments ----
        uint32_t pA[4][4], pB[4][4];
        float rs0 = 0.f, rs1 = 0.f, rs2 = 0.f, rs3 = 0.f;
        #pragma unroll
        for (int nt = 0; nt < 8; nt++) {
            #pragma unroll
            for (int r = 0; r < 4; r++) {
                sA[nt][r] = ex2(sA[nt][r]);
                sB[nt][r] = ex2(sB[nt][r]);
            }
            rs0 += sA[nt][0] + sA[nt][1];
            rs1 += sA[nt][2] + sA[nt][3];
            rs2 += sB[nt][0] + sB[nt][1];
            rs3 += sB[nt][2] + sB[nt][3];
        }
        lA0 += rs0; lA1 += rs1; lB0 += rs2; lB1 += rs3;

        #pragma unroll
        for (int kk = 0; kk < 4; kk++) {
            pA[kk][0] = pack_h2(sA[2*kk  ][0], sA[2*kk  ][1]);
            pA[kk][1] = pack_h2(sA[2*kk  ][2], sA[2*kk  ][3]);
            pA[kk][2] = pack_h2(sA[2*kk+1][0], sA[2*kk+1][1]);
            pA[kk][3] = pack_h2(sA[2*kk+1][2], sA[2*kk+1][3]);
            pB[kk][0] = pack_h2(sB[2*kk  ][0], sB[2*kk  ][1]);
            pB[kk][1] = pack_h2(sB[2*kk  ][2], sB[2*kk  ][3]);
            pB[kk][2] = pack_h2(sB[2*kk+1][0], sB[2*kk+1][1]);
            pB[kk][3] = pack_h2(sB[2*kk+1][2], sB[2*kk+1][3]);
        }

        // ---- O += P V  (B from transposed V: adjacent j in half2) ----
        #pragma unroll
        for (int kk = 0; kk < 4; kk++) {
            const int j0 = kk*16 + 2*la3;
            #pragma unroll
            for (int nt = 0; nt < 8; nt++) {
                const __half* vr = vp + (nt*8 + lr)*RS + j0;
                const uint32_t b0 = lds_b32(vr);
                const uint32_t b1 = lds_b32(vr + 8);
                mma_f16(oA[nt], pA[kk][0], pA[kk][1], pA[kk][2], pA[kk][3], b0, b1);
                mma_f16(oB[nt], pB[kk][0], pB[kk][1], pB[kk][2], pB[kk][3], b0, b1);
            }
        }
        __syncthreads();   // stage t&1 free before next prefetch overwrites it
    }

    // ---- quad reduction of row sums + epilogue ----
    lA0 += __shfl_xor_sync(0xffffffffu, lA0, 1);
    lA0 += __shfl_xor_sync(0xffffffffu, lA0, 2);
    lA1 += __shfl_xor_sync(0xffffffffu, lA1, 1);
    lA1 += __shfl_xor_sync(0xffffffffu, lA1, 2);
    lB0 += __shfl_xor_sync(0xffffffffu, lB0, 1);
    lB0 += __shfl_xor_sync(0xffffffffu, lB0, 2);
    lB1 += __shfl_xor_sync(0xffffffffu, lB1, 1);
    lB1 += __shfl_xor_sync(0xffffffffu, lB1, 2);
    const float iA0 = 1.f / lA0, iA1 = 1.f / lA1;
    const float iB0 = 1.f / lB0, iB1 = 1.f / lB1;

    float* Ob = out + (size_t)(b*TT + qt*BQ)*HH;
    #pragma unroll
    for (int nt = 0; nt < 8; nt++) {
        const int col = nt*8 + 2*la3;
        *(float2*)(Ob + (wr0 + lr      )*HH + col) = make_float2(oA[nt][0]*iA0, oA[nt][1]*iA0);
        *(float2*)(Ob + (wr0 + lr +  8 )*HH + col) = make_float2(oA[nt][2]*iA1, oA[nt][3]*iA1);
        *(float2*)(Ob + (wr0 + lr + 16 )*HH + col) = make_float2(oB[nt][0]*iB0, oB[nt][1]*iB0);
        *(float2*)(Ob + (wr0 + lr + 24 )*HH + col) = make_float2(oB[nt][2]*iB1, oB[nt][3]*iB1);
    }
}

// ---------------------------------------------------------------------------
extern "C" void kernel_launch(void* const* d_in, const int* in_sizes, int n_in,
                              void* d_out, int out_size)
{
    const float* x  = (const float*)d_in[0];
    const float* Wk = (const float*)d_in[1];
    const float* Wq = (const float*)d_in[2];
    const float* Wv = (const float*)d_in[3];
    float* out = (float*)d_out;

    proj_kernel<<<BT/32, 256>>>(x, Wk, Wq, Wv);

    cudaFuncSetAttribute(attn_kernel,
                         cudaFuncAttributeMaxDynamicSharedMemorySize, SM_BYTES);
    dim3 grid(TT/BQ, BB);
    attn_kernel<<<grid, 128, SM_BYTES>>>(out);
}

// round 6
// speedup vs baseline: 8.7369x; 1.2060x over previous
#include <cuda_runtime.h>
#include <cuda_fp16.h>
#include <cstdint>
#include <math.h>

#define BB 16
#define TT 2048
#define CC 68
#define HH 64
#define BT (BB*TT)
#define BQ 128
#define BK 64
#define NKT (TT/BK)     // 32
#define RS  72          // attn smem row stride in halves

// fp16 scratch: Q (pre-scaled by log2e/8), K row-major [t][h]; V transposed [b][h][t].
__device__ __align__(16) __half g_Q[BT*HH];
__device__ __align__(16) __half g_K[BT*HH];
__device__ __align__(16) __half g_Vt[BB*HH*TT];

__device__ __forceinline__ uint32_t smem_u32(const void* p) {
    uint32_t a;
    asm("{ .reg .u64 t; cvta.to.shared.u64 t, %1; cvt.u32.u64 %0, t; }" : "=r"(a) : "l"(p));
    return a;
}
__device__ __forceinline__ void cpa16(uint32_t dst, const void* src) {
    asm volatile("cp.async.cg.shared.global [%0], [%1], 16;" :: "r"(dst), "l"(src) : "memory");
}
__device__ __forceinline__ void cpa_commit() {
    asm volatile("cp.async.commit_group;" ::: "memory");
}
__device__ __forceinline__ float ex2(float x) {
    float r; asm("ex2.approx.f32 %0, %1;" : "=f"(r) : "f"(x)); return r;
}
__device__ __forceinline__ uint32_t pack_h2(float x, float y) {   // lo=x, hi=y
    uint32_t r; asm("cvt.rn.f16x2.f32 %0, %1, %2;" : "=r"(r) : "f"(y), "f"(x)); return r;
}
__device__ __forceinline__ uint32_t lds_b32(const __half* p) {
    return *(const uint32_t*)p;
}
__device__ __forceinline__ void mma_f16(float d[4],
                                        uint32_t a0, uint32_t a1, uint32_t a2, uint32_t a3,
                                        uint32_t b0, uint32_t b1) {
    asm volatile(
        "mma.sync.aligned.m16n8k16.row.col.f32.f16.f16.f32 "
        "{%0,%1,%2,%3}, {%4,%5,%6,%7}, {%8,%9}, {%0,%1,%2,%3};"
        : "+f"(d[0]), "+f"(d[1]), "+f"(d[2]), "+f"(d[3])
        : "r"(a0), "r"(a1), "r"(a2), "r"(a3), "r"(b0), "r"(b1));
}

// ---------------------------------------------------------------------------
// Kernel 1: tensor-core QKV projection.
// CTA = 128 x-rows; x[128,80] fp16 (K zero-padded) @ W^T[192,80] fp16.
// Q scale (log2e/8) folded into Wq. V written transposed to g_Vt[b][h][t].
// ---------------------------------------------------------------------------
#define PSTR 88     // smem row stride (halves) for x and W tiles
#define VSTR 136    // smem row stride for V-transpose staging

__global__ __launch_bounds__(256) void proj_kernel(
    const float* __restrict__ x,
    const float* __restrict__ Wk,
    const float* __restrict__ Wq,
    const float* __restrict__ Wv)
{
    extern __shared__ __half ps[];
    __half* sx  = ps;               // [128][PSTR]
    __half* sw  = ps + 128*PSTR;    // [192][PSTR]  W^T: [n][k]
    __half* svt = ps;               // reused later: [64][VSTR]

    const int tid  = threadIdx.x;
    const int row0 = blockIdx.x * 128;

    // zero the k-pad columns 68..79
    if (tid < 192) {
        __half* base = (tid < 128) ? (sx + tid*PSTR) : (sw + (tid-128)*PSTR);
        *(uint2*)(base + 68) = make_uint2(0u,0u);
        // also pad rows 128..191 of sw for the first 128 tids' counterpart
    }
    if (tid < 192) *(uint2*)(sw + tid*PSTR + 68) = make_uint2(0u,0u);
    if (tid < 128) { *(uint2*)(sx + tid*PSTR + 68) = make_uint2(0u,0u);
                     *(uint2*)(sx + tid*PSTR + 72) = make_uint2(0u,0u);
                     *(uint2*)(sx + tid*PSTR + 76) = make_uint2(0u,0u); }
    if (tid < 192) { *(uint2*)(sw + tid*PSTR + 72) = make_uint2(0u,0u);
                     *(uint2*)(sw + tid*PSTR + 76) = make_uint2(0u,0u); }

    // load x tile, fp32 -> fp16 (17 float4 chunks per row)
    for (int i = tid; i < 128*17; i += 256) {
        const int row = i / 17, c = i % 17;
        const float4 v = *(const float4*)(x + (size_t)(row0 + row)*CC + c*4);
        uint2 h;
        h.x = pack_h2(v.x, v.y);
        h.y = pack_h2(v.z, v.w);
        *(uint2*)(sx + row*PSTR + c*4) = h;
    }

    // load W's transposed into sw[n][k]; fold qscale into Wq
    const float qscale = 0.125f * 1.4426950408889634f;
    for (int i = tid; i < 3*CC*HH; i += 256) {
        const int m = i / (CC*HH), r = i % (CC*HH);
        const int c = r >> 6, h = r & 63;
        const float* Wm = (m == 0) ? Wk : ((m == 1) ? Wq : Wv);
        float w = Wm[c*HH + h];
        if (m == 1) w *= qscale;
        sw[(m*64 + h)*PSTR + c] = __float2half_rn(w);
    }
    __syncthreads();

    const int wid = tid >> 5, lane = tid & 31;
    const int lr = lane >> 2, la3 = lane & 3;
    const int wr = wid * 16;

    // A fragments: 5 k-steps
    uint32_t a[5][4];
    #pragma unroll
    for (int k = 0; k < 5; k++) {
        const int c0 = k*16 + 2*la3;
        a[k][0] = lds_b32(sx + (wr + lr    )*PSTR + c0    );
        a[k][1] = lds_b32(sx + (wr + lr + 8)*PSTR + c0    );
        a[k][2] = lds_b32(sx + (wr + lr    )*PSTR + c0 + 8);
        a[k][3] = lds_b32(sx + (wr + lr + 8)*PSTR + c0 + 8);
    }

    float o[24][4];
    #pragma unroll
    for (int nt = 0; nt < 24; nt++)
        #pragma unroll
        for (int r = 0; r < 4; r++) o[nt][r] = 0.f;

    #pragma unroll
    for (int k = 0; k < 5; k++) {
        const int c0 = k*16 + 2*la3;
        #pragma unroll
        for (int nt = 0; nt < 24; nt++) {
            const __half* wr_ = sw + (nt*8 + lr)*PSTR + c0;
            mma_f16(o[nt], a[k][0], a[k][1], a[k][2], a[k][3],
                    lds_b32(wr_), lds_b32(wr_ + 8));
        }
    }

    // K (nt 0..7) and Q (nt 8..15): direct half2 global stores
    const int rg = row0 + wr + lr;
    #pragma unroll
    for (int nt = 0; nt < 8; nt++) {
        const int col = nt*8 + 2*la3;
        *(uint32_t*)(g_K + (size_t)rg*HH + col)       = pack_h2(o[nt][0], o[nt][1]);
        *(uint32_t*)(g_K + (size_t)(rg+8)*HH + col)   = pack_h2(o[nt][2], o[nt][3]);
        *(uint32_t*)(g_Q + (size_t)rg*HH + col)       = pack_h2(o[nt+8][0], o[nt+8][1]);
        *(uint32_t*)(g_Q + (size_t)(rg+8)*HH + col)   = pack_h2(o[nt+8][2], o[nt+8][3]);
    }

    // V (nt 16..23): stage transposed in smem, then wide global writes
    __syncthreads();   // sx region (svt) free: all a-frags long consumed, but other warps must be past extraction
    #pragma unroll
    for (int nt = 16; nt < 24; nt++) {
        const int h = (nt-16)*8 + 2*la3;
        const int t = wr + lr;
        svt[(h  )*VSTR + t    ] = __float2half_rn(o[nt][0]);
        svt[(h+1)*VSTR + t    ] = __float2half_rn(o[nt][1]);
        svt[(h  )*VSTR + t + 8] = __float2half_rn(o[nt][2]);
        svt[(h+1)*VSTR + t + 8] = __float2half_rn(o[nt][3]);
    }
    __syncthreads();

    const int b  = blockIdx.x >> 4;
    const int t0 = (blockIdx.x & 15) * 128;
    for (int i = tid; i < 1024; i += 256) {         // 64 h x 16 chunks of 8 halves
        const int h = i >> 4, ch = i & 15;
        *(uint4*)(g_Vt + ((size_t)b*HH + h)*TT + t0 + ch*8) =
            *(const uint4*)(svt + h*VSTR + ch*8);
    }
}
#define PROJ_SMEM ((128*PSTR + 192*PSTR)*2)   // 56320 bytes

// ---------------------------------------------------------------------------
// Kernel 2: flash attention, fp16 m16n8k16, 4 warps x m32, 3-stage KV ring,
// one __syncthreads per tile.  P never touches smem.
// ---------------------------------------------------------------------------
#define OFF_Q   0
#define STG(s)  (BQ*RS + (s)*2*BK*RS)         // K stage s
#define STGV(s) (STG(s) + BK*RS)              // V stage s
#define SM_HALVES (BQ*RS + 6*BK*RS)           // 36864
#define SM_BYTES  (SM_HALVES*2)               // 73728

__global__ __launch_bounds__(128, 2) void attn_kernel(float* __restrict__ out)
{
    extern __shared__ __half sm[];
    const uint32_t sb = smem_u32(sm);

    const int b    = blockIdx.y;
    const int qt   = blockIdx.x;
    const int tid  = threadIdx.x;
    const int wid  = tid >> 5;
    const int lane = tid & 31;
    const int lr   = lane >> 2;
    const int la3  = lane & 3;
    const int wr0  = wid * 32;

    const __half* Qb  = g_Q  + (size_t)(b*TT + qt*BQ)*HH;
    const __half* Kb  = g_K  + (size_t)b*TT*HH;
    const __half* Vtb = g_Vt + (size_t)b*HH*TT;

    // prologue: Q (group), KV0 (group), KV1 (group)
    #pragma unroll
    for (int i = 0; i < 8; i++) {
        const int g = tid + i*128, row = g >> 3, ch = g & 7;
        cpa16(sb + (uint32_t)(OFF_Q + row*RS + ch*8)*2u, Qb + row*HH + ch*8);
    }
    cpa_commit();
    #pragma unroll
    for (int st = 0; st < 2; st++) {
        const __half* Ks = Kb + (size_t)st*BK*HH;
        const __half* Vs = Vtb + st*BK;
        #pragma unroll
        for (int i = 0; i < 4; i++) {
            const int g = tid + i*128, row = g >> 3, ch = g & 7;
            cpa16(sb + (STG(st)  + (uint32_t)(row*RS + ch*8))*2u, Ks + row*HH + ch*8);
            cpa16(sb + (STGV(st) + (uint32_t)(row*RS + ch*8))*2u, Vs + (size_t)row*TT + ch*8);
        }
        cpa_commit();
    }
    asm volatile("cp.async.wait_group 2;" ::: "memory");   // Q done
    __syncthreads();

    uint32_t qa[4][8];
    #pragma unroll
    for (int k = 0; k < 4; k++) {
        const int c0 = k*16 + 2*la3;
        const __half* q0 = sm + OFF_Q + c0;
        qa[k][0] = lds_b32(q0 + (wr0 + lr      )*RS    );
        qa[k][1] = lds_b32(q0 + (wr0 + lr +  8 )*RS    );
        qa[k][2] = lds_b32(q0 + (wr0 + lr      )*RS + 8);
        qa[k][3] = lds_b32(q0 + (wr0 + lr +  8 )*RS + 8);
        qa[k][4] = lds_b32(q0 + (wr0 + lr + 16 )*RS    );
        qa[k][5] = lds_b32(q0 + (wr0 + lr + 24 )*RS    );
        qa[k][6] = lds_b32(q0 + (wr0 + lr + 16 )*RS + 8);
        qa[k][7] = lds_b32(q0 + (wr0 + lr + 24 )*RS + 8);
    }

    float oA[8][4], oB[8][4];
    #pragma unroll
    for (int nt = 0; nt < 8; nt++)
        #pragma unroll
        for (int r = 0; r < 4; r++) { oA[nt][r] = 0.f; oB[nt][r] = 0.f; }
    float lA0 = 0.f, lA1 = 0.f, lB0 = 0.f, lB1 = 0.f;

    for (int t = 0; t < NKT; t++) {
        // KV(t) ready: leave only the newest group (KV(t+1)) pending
        if (t + 1 < NKT) asm volatile("cp.async.wait_group 1;" ::: "memory");
        else             asm volatile("cp.async.wait_group 0;" ::: "memory");
        __syncthreads();   // KV(t) visible; stage (t+2)%3's readers (tile t-1) done

        if (t + 2 < NKT) {
            const int st = (t+2) % 3;
            const __half* Ks = Kb + (size_t)(t+2)*BK*HH;
            const __half* Vs = Vtb + (t+2)*BK;
            #pragma unroll
            for (int i = 0; i < 4; i++) {
                const int g = tid + i*128, row = g >> 3, ch = g & 7;
                cpa16(sb + (STG(st)  + (uint32_t)(row*RS + ch*8))*2u, Ks + row*HH + ch*8);
                cpa16(sb + (STGV(st) + (uint32_t)(row*RS + ch*8))*2u, Vs + (size_t)row*TT + ch*8);
            }
            cpa_commit();
        }

        const __half* kp = sm + STG(t % 3);
        const __half* vp = sm + STGV(t % 3);

        // ---- S = Q K^T ----
        float sA[8][4], sB[8][4];
        #pragma unroll
        for (int nt = 0; nt < 8; nt++)
            #pragma unroll
            for (int r = 0; r < 4; r++) { sA[nt][r] = 0.f; sB[nt][r] = 0.f; }

        #pragma unroll
        for (int k = 0; k < 4; k++) {
            const int c0 = k*16 + 2*la3;
            #pragma unroll
            for (int nt = 0; nt < 8; nt++) {
                const __half* kr = kp + (nt*8 + lr)*RS + c0;
                const uint32_t b0 = lds_b32(kr);
                const uint32_t b1 = lds_b32(kr + 8);
                mma_f16(sA[nt], qa[k][0], qa[k][1], qa[k][2], qa[k][3], b0, b1);
                mma_f16(sB[nt], qa[k][4], qa[k][5], qa[k][6], qa[k][7], b0, b1);
            }
        }

        // ---- P = exp2(S); fp32 row sums; pack to A-fragments ----
        uint32_t pA[4][4], pB[4][4];
        float rs0 = 0.f, rs1 = 0.f, rs2 = 0.f, rs3 = 0.f;
        #pragma unroll
        for (int nt = 0; nt < 8; nt++) {
            #pragma unroll
            for (int r = 0; r < 4; r++) {
                sA[nt][r] = ex2(sA[nt][r]);
                sB[nt][r] = ex2(sB[nt][r]);
            }
            rs0 += sA[nt][0] + sA[nt][1];
            rs1 += sA[nt][2] + sA[nt][3];
            rs2 += sB[nt][0] + sB[nt][1];
            rs3 += sB[nt][2] + sB[nt][3];
        }
        lA0 += rs0; lA1 += rs1; lB0 += rs2; lB1 += rs3;

        #pragma unroll
        for (int kk = 0; kk < 4; kk++) {
            pA[kk][0] = pack_h2(sA[2*kk  ][0], sA[2*kk  ][1]);
            pA[kk][1] = pack_h2(sA[2*kk  ][2], sA[2*kk  ][3]);
            pA[kk][2] = pack_h2(sA[2*kk+1][0], sA[2*kk+1][1]);
            pA[kk][3] = pack_h2(sA[2*kk+1][2], sA[2*kk+1][3]);
            pB[kk][0] = pack_h2(sB[2*kk  ][0], sB[2*kk  ][1]);
            pB[kk][1] = pack_h2(sB[2*kk  ][2], sB[2*kk  ][3]);
            pB[kk][2] = pack_h2(sB[2*kk+1][0], sB[2*kk+1][1]);
            pB[kk][3] = pack_h2(sB[2*kk+1][2], sB[2*kk+1][3]);
        }

        // ---- O += P V ----
        #pragma unroll
        for (int kk = 0; kk < 4; kk++) {
            const int j0 = kk*16 + 2*la3;
            #pragma unroll
            for (int nt = 0; nt < 8; nt++) {
                const __half* vr = vp + (nt*8 + lr)*RS + j0;
                const uint32_t b0 = lds_b32(vr);
                const uint32_t b1 = lds_b32(vr + 8);
                mma_f16(oA[nt], pA[kk][0], pA[kk][1], pA[kk][2], pA[kk][3], b0, b1);
                mma_f16(oB[nt], pB[kk][0], pB[kk][1], pB[kk][2], pB[kk][3], b0, b1);
            }
        }
        // no end-of-tile sync: next iteration's sync fences stage reuse
    }

    lA0 += __shfl_xor_sync(0xffffffffu, lA0, 1);
    lA0 += __shfl_xor_sync(0xffffffffu, lA0, 2);
    lA1 += __shfl_xor_sync(0xffffffffu, lA1, 1);
    lA1 += __shfl_xor_sync(0xffffffffu, lA1, 2);
    lB0 += __shfl_xor_sync(0xffffffffu, lB0, 1);
    lB0 += __shfl_xor_sync(0xffffffffu, lB0, 2);
    lB1 += __shfl_xor_sync(0xffffffffu, lB1, 1);
    lB1 += __shfl_xor_sync(0xffffffffu, lB1, 2);
    const float iA0 = 1.f / lA0, iA1 = 1.f / lA1;
    const float iB0 = 1.f / lB0, iB1 = 1.f / lB1;

    float* Ob = out + (size_t)(b*TT + qt*BQ)*HH;
    #pragma unroll
    for (int nt = 0; nt < 8; nt++) {
        const int col = nt*8 + 2*la3;
        *(float2*)(Ob + (wr0 + lr      )*HH + col) = make_float2(oA[nt][0]*iA0, oA[nt][1]*iA0);
        *(float2*)(Ob + (wr0 + lr +  8 )*HH + col) = make_float2(oA[nt][2]*iA1, oA[nt][3]*iA1);
        *(float2*)(Ob + (wr0 + lr + 16 )*HH + col) = make_float2(oB[nt][0]*iB0, oB[nt][1]*iB0);
        *(float2*)(Ob + (wr0 + lr + 24 )*HH + col) = make_float2(oB[nt][2]*iB1, oB[nt][3]*iB1);
    }
}

// ---------------------------------------------------------------------------
extern "C" void kernel_launch(void* const* d_in, const int* in_sizes, int n_in,
                              void* d_out, int out_size)
{
    const float* x  = (const float*)d_in[0];
    const float* Wk = (const float*)d_in[1];
    const float* Wq = (const float*)d_in[2];
    const float* Wv = (const float*)d_in[3];
    float* out = (float*)d_out;

    cudaFuncSetAttribute(proj_kernel,
                         cudaFuncAttributeMaxDynamicSharedMemorySize, PROJ_SMEM);
    proj_kernel<<<BT/128, 256, PROJ_SMEM>>>(x, Wk, Wq, Wv);

    cudaFuncSetAttribute(attn_kernel,
                         cudaFuncAttributeMaxDynamicSharedMemorySize, SM_BYTES);
    dim3 grid(TT/BQ, BB);
    attn_kernel<<<grid, 128, SM_BYTES>>>(out);
}